// round 13
// baseline (speedup 1.0000x reference)
#include <cuda_runtime.h>
#include <cuda_bf16.h>
#include <cstdint>

// Problem constants
#define B_  8
#define N_  1024
#define C_  256
#define H_  8
#define BH_ (B_ * H_)
#define HEAD_ELEMS_ 524288
#define SCALE_ 0.0625f

// Scratch (device globals)
__device__ float g_q[BH_ * N_ * 64];
__device__ float g_k[BH_ * N_ * 64];
__device__ float g_part[2048];
__device__ float g_stats[16 * 2];
__device__ int   g_ticket;
__device__ __nv_bfloat16 g_qh[BH_ * N_ * 64];
__device__ __nv_bfloat16 g_ql[BH_ * N_ * 64];
__device__ __nv_bfloat16 g_kh[BH_ * N_ * 64];
__device__ __nv_bfloat16 g_kl[BH_ * N_ * 64];
__device__ __nv_bfloat16 g_xh[8192 * 256];
__device__ __nv_bfloat16 g_xl[8192 * 256];
__device__ __nv_bfloat16 g_wh[1024 * 256];
__device__ __nv_bfloat16 g_wl[1024 * 256];

// ---------------------------------------------------------------------------
// helpers
// ---------------------------------------------------------------------------
__device__ __forceinline__ uint32_t smem_u32(const void* p) {
    uint32_t a;
    asm("{ .reg .u64 t; cvta.to.shared.u64 t, %1; cvt.u32.u64 %0, t; }" : "=r"(a) : "l"(p));
    return a;
}
__device__ __forceinline__ void ldsm_x4(uint32_t* r, uint32_t addr) {
    asm volatile("ldmatrix.sync.aligned.m8n8.x4.shared.b16 {%0,%1,%2,%3}, [%4];"
                 : "=r"(r[0]), "=r"(r[1]), "=r"(r[2]), "=r"(r[3]) : "r"(addr));
}
__device__ __forceinline__ void mma_bf16(float* c, const uint32_t* a, uint32_t b0, uint32_t b1) {
    asm volatile("mma.sync.aligned.m16n8k16.row.col.f32.bf16.bf16.f32 "
                 "{%0,%1,%2,%3},{%4,%5,%6,%7},{%8,%9},{%0,%1,%2,%3};"
                 : "+f"(c[0]), "+f"(c[1]), "+f"(c[2]), "+f"(c[3])
                 : "r"(a[0]), "r"(a[1]), "r"(a[2]), "r"(a[3]), "r"(b0), "r"(b1));
}
__device__ __forceinline__ void cp16(uint32_t d, const void* s) {
    asm volatile("cp.async.cg.shared.global [%0], [%1], 16;" :: "r"(d), "l"(s));
}
#define CP_COMMIT() asm volatile("cp.async.commit_group;" ::: "memory")
#define CP_WAIT1()  asm volatile("cp.async.wait_group 1;" ::: "memory")
#define CP_WAIT0()  asm volatile("cp.async.wait_group 0;" ::: "memory")

// ---------------------------------------------------------------------------
// Kernel 0: bf16 hi/lo split of x and [qw;kw]
// ---------------------------------------------------------------------------
__global__ void __launch_bounds__(256) split_inputs_kernel(const float* __restrict__ x,
                                                           const float* __restrict__ qw,
                                                           const float* __restrict__ kw) {
    int idx = (blockIdx.x * 256 + threadIdx.x) * 4;
    const float* src;
    __nv_bfloat16 *dh, *dl;
    int off;
    if (idx < 2097152) {
        src = x; off = idx; dh = g_xh; dl = g_xl;
    } else if (idx < 2097152 + 131072) {
        src = qw; off = idx - 2097152; dh = g_wh; dl = g_wl;
    } else {
        src = kw; off = idx - 2097152 - 131072; dh = g_wh + 131072; dl = g_wl + 131072;
    }
    float4 v = *(const float4*)(src + off);
    __nv_bfloat16 h0 = __float2bfloat16(v.x), h1 = __float2bfloat16(v.y);
    __nv_bfloat16 h2 = __float2bfloat16(v.z), h3 = __float2bfloat16(v.w);
    __nv_bfloat162 hv0, hv1, lv0, lv1;
    hv0.x = h0; hv0.y = h1; hv1.x = h2; hv1.y = h3;
    lv0.x = __float2bfloat16(v.x - __bfloat162float(h0));
    lv0.y = __float2bfloat16(v.y - __bfloat162float(h1));
    lv1.x = __float2bfloat16(v.z - __bfloat162float(h2));
    lv1.y = __float2bfloat16(v.w - __bfloat162float(h3));
    *(__nv_bfloat162*)(dh + off)     = hv0;
    *(__nv_bfloat162*)(dh + off + 2) = hv1;
    *(__nv_bfloat162*)(dl + off)     = lv0;
    *(__nv_bfloat162*)(dl + off + 2) = lv1;
}

// ---------------------------------------------------------------------------
// Kernel 1: q/k = x @ w^T, cp.async 2-stage pipeline (R10-proven).
// Epilogue folds BN partial stats; last CTA (ticket) finalizes g_stats.
// ---------------------------------------------------------------------------
#define QK_STAGE 40960
#define QK_AHI 0
#define QK_ALO 10240
#define QK_BHI 20480
#define QK_BLO 30720
#define QK_SMEM (2 * QK_STAGE)   // 81920

__global__ void __launch_bounds__(256, 2) gemm_qk_mma() {
    extern __shared__ char smq[];
    const uint32_t sb = smem_u32(smq);
    const int tid = threadIdx.x;
    const int wid = tid >> 5, lane = tid & 31;
    const int bx = blockIdx.x, by = blockIdx.y, bz = blockIdx.z;
    const int m0 = by * 128, n0 = bx * 128;
    const __nv_bfloat16* Bh = g_wh + (size_t)(bz * 512) * 256;
    const __nv_bfloat16* Bl = g_wl + (size_t)(bz * 512) * 256;

    auto stage = [&](int kc, int buf) {
        uint32_t base = sb + buf * QK_STAGE;
#pragma unroll
        for (int i = 0; i < 2; i++) {
            int idx = tid + i * 256;
            int row = idx >> 2, c = idx & 3;
            uint32_t so = (uint32_t)row * 80 + c * 16;
            size_t goA = (size_t)(m0 + row) * 256 + kc * 32 + c * 8;
            size_t goB = (size_t)(n0 + row) * 256 + kc * 32 + c * 8;
            cp16(base + QK_AHI + so, g_xh + goA);
            cp16(base + QK_ALO + so, g_xl + goA);
            cp16(base + QK_BHI + so, Bh + goB);
            cp16(base + QK_BLO + so, Bl + goB);
        }
    };

    const int wm = (wid & 3) * 32;
    const int wn = (wid >> 2) * 64;
    const int l07 = lane & 7;
    const int b3 = (lane >> 3) & 1;
    const int b4 = lane >> 4;
    const uint32_t aOff = (uint32_t)(wm + b3 * 8 + l07) * 80 + b4 * 16;
    const uint32_t bOff = (uint32_t)(wn + b4 * 8 + l07) * 80 + b3 * 16;

    float acc[2][8][4];
#pragma unroll
    for (int f = 0; f < 2; f++)
#pragma unroll
        for (int g = 0; g < 8; g++)
#pragma unroll
            for (int j = 0; j < 4; j++) acc[f][g][j] = 0.f;

    stage(0, 0);
    CP_COMMIT();

#pragma unroll 1
    for (int kc = 0; kc < 8; kc++) {
        if (kc < 7) { stage(kc + 1, (kc + 1) & 1); CP_COMMIT(); CP_WAIT1(); }
        else CP_WAIT0();
        __syncthreads();
        uint32_t base = sb + (kc & 1) * QK_STAGE;
#pragma unroll
        for (int ks = 0; ks < 2; ks++) {
            uint32_t ah[2][4], al[2][4];
#pragma unroll
            for (int f = 0; f < 2; f++) {
                ldsm_x4(ah[f], base + QK_AHI + aOff + f * 1280 + ks * 32);
                ldsm_x4(al[f], base + QK_ALO + aOff + f * 1280 + ks * 32);
            }
            uint32_t bhf[4][4], blf[4][4];
#pragma unroll
            for (int p = 0; p < 4; p++) {
                ldsm_x4(bhf[p], base + QK_BHI + bOff + p * 1280 + ks * 32);
                ldsm_x4(blf[p], base + QK_BLO + bOff + p * 1280 + ks * 32);
            }
#pragma unroll
            for (int f = 0; f < 2; f++)
#pragma unroll
                for (int p = 0; p < 4; p++) {
                    mma_bf16(acc[f][2 * p],     ah[f], bhf[p][0], bhf[p][1]);
                    mma_bf16(acc[f][2 * p],     al[f], bhf[p][0], bhf[p][1]);
                    mma_bf16(acc[f][2 * p],     ah[f], blf[p][0], blf[p][1]);
                    mma_bf16(acc[f][2 * p + 1], ah[f], bhf[p][2], bhf[p][3]);
                    mma_bf16(acc[f][2 * p + 1], al[f], bhf[p][2], bhf[p][3]);
                    mma_bf16(acc[f][2 * p + 1], ah[f], blf[p][2], blf[p][3]);
                }
        }
        __syncthreads();
    }

    float* outp = bz ? g_k : g_q;
    const int r0 = m0 + wm + (lane >> 2);
    const int c0 = n0 + wn + (lane & 3) * 2;
    float s1 = 0.f, s2 = 0.f;
#pragma unroll
    for (int f = 0; f < 2; f++)
#pragma unroll
        for (int g = 0; g < 8; g++) {
            int col = c0 + g * 8;
            int h = col >> 6, d = col & 63;
#pragma unroll
            for (int u = 0; u < 2; u++) {
                float v0 = acc[f][g][u * 2], v1 = acc[f][g][u * 2 + 1];
                s1 += v0 + v1;
                s2 += v0 * v0 + v1 * v1;
                int row = r0 + f * 16 + u * 8;
                int bb = row >> 10, nn = row & 1023;
                float* dst = outp + ((size_t)(bb * H_ + h) << 16) + nn * 64 + d;
                *(float2*)dst = make_float2(v0, v1);
            }
        }
#pragma unroll
    for (int o = 16; o; o >>= 1) {
        s1 += __shfl_xor_sync(0xffffffffu, s1, o);
        s2 += __shfl_xor_sync(0xffffffffu, s2, o);
    }
    __shared__ float wsum[8], wsq[8];
    __shared__ int islast;
    if (lane == 0) { wsum[wid] = s1; wsq[wid] = s2; }
    __syncthreads();
    if (tid == 0) {
        int slot = ((bz * 4 + bx) * 64 + by) * 4;
        g_part[slot + 0] = wsum[0] + wsum[1] + wsum[2] + wsum[3];
        g_part[slot + 1] = wsq[0] + wsq[1] + wsq[2] + wsq[3];
        g_part[slot + 2] = wsum[4] + wsum[5] + wsum[6] + wsum[7];
        g_part[slot + 3] = wsq[4] + wsq[5] + wsq[6] + wsq[7];
        __threadfence();
        islast = (atomicAdd(&g_ticket, 1) == 511);
    }
    __syncthreads();
    if (islast) {
        __threadfence();
        if (tid < 16) {
            int t = tid >> 3, h = tid & 7;
            int bx2 = h >> 1, sel = h & 1;
            float a = 0.f, c2 = 0.f;
            for (int by2 = 0; by2 < 64; by2++) {
                int slot = ((t * 4 + bx2) * 64 + by2) * 4 + sel * 2;
                a += g_part[slot];
                c2 += g_part[slot + 1];
            }
            float mean = a * (1.f / (float)HEAD_ELEMS_);
            float var = c2 * (1.f / (float)HEAD_ELEMS_) - mean * mean;
            g_stats[tid * 2] = mean;
            g_stats[tid * 2 + 1] = rsqrtf(var + 1e-5f);
        }
        if (tid == 0) g_ticket = 0;
    }
}

// ---------------------------------------------------------------------------
// Kernel 2: BN + L2 normalize; emit bf16 hi/lo split.
// ---------------------------------------------------------------------------
__global__ void __launch_bounds__(256) normalize_kernel(const float* __restrict__ bnw,
                                                        const float* __restrict__ bnb) {
    int gw = (blockIdx.x * blockDim.x + threadIdx.x) >> 5;
    int lane = threadIdx.x & 31;
    int t = gw >> 16;
    int rem = gw & 65535;
    int h = (rem >> 10) & 7;
    const float* p = (t ? g_k : g_q) + (size_t)rem * 64;
    float mean = g_stats[(t * 8 + h) * 2];
    float rstd = g_stats[(t * 8 + h) * 2 + 1];
    float w = bnw[h], bia = bnb[h];
    float2 v = *(const float2*)(p + lane * 2);
    float x0 = (v.x - mean) * rstd * w + bia;
    float x1 = (v.y - mean) * rstd * w + bia;
    float ss = x0 * x0 + x1 * x1;
#pragma unroll
    for (int o = 16; o; o >>= 1) ss += __shfl_xor_sync(0xffffffffu, ss, o);
    float inv = 1.f / fmaxf(sqrtf(ss), 1e-12f);
    x0 *= inv; x1 *= inv;

    __nv_bfloat16 h0 = __float2bfloat16(x0);
    __nv_bfloat16 h1 = __float2bfloat16(x1);
    __nv_bfloat16 l0 = __float2bfloat16(x0 - __bfloat162float(h0));
    __nv_bfloat16 l1 = __float2bfloat16(x1 - __bfloat162float(h1));
    size_t off = (size_t)rem * 64 + lane * 2;
    __nv_bfloat162 hv; hv.x = h0; hv.y = h1;
    __nv_bfloat162 lv; lv.x = l0; lv.y = l1;
    if (t) {
        *(__nv_bfloat162*)(g_kh + off) = hv;
        *(__nv_bfloat162*)(g_kl + off) = lv;
    } else {
        *(__nv_bfloat162*)(g_qh + off) = hv;
        *(__nv_bfloat162*)(g_ql + off) = lv;
    }
}

// ---------------------------------------------------------------------------
// Kernel 3 (fused v4): R12 GEMM (smem-staged Q, ldmatrix) + R7 warp-private
// sparsemax (slab overlapping dead Q buffers; NO block barriers in the
// Michelot loop) + R12 sector-coalesced register write.
// smem: K 9216 | slab/Q union 131200 | tauS 128  = 140544 (R10-proven size)
// ---------------------------------------------------------------------------
#define FS_K_HI 0
#define FS_K_LO 4608
#define FS_Q    9216                       // Q double buffer, dead after GEMM
#define FS_QSTG 18432
#define FS_SLAB 9216                       // overlaps Q region
#define SROW 1025
#define FS_TAUS (FS_SLAB + 32 * SROW * 4)  // 140416
#define FS_SMEM (FS_TAUS + 128)            // 140544

__global__ void __launch_bounds__(512, 1) fused_scores_sparsemax(float* __restrict__ out) {
    extern __shared__ char smf[];
    const uint32_t sb = smem_u32(smf);
    float* S_s  = (float*)(smf + FS_SLAB);
    float* tauS = (float*)(smf + FS_TAUS);

    const int tid = threadIdx.x;
    const int w = tid >> 5, lane = tid & 31;
    const int wm = w & 1, wn = w >> 1;           // row-half, col-group
    const int bh = blockIdx.y;
    const int m0 = blockIdx.x * 32;
    const size_t hbase = (size_t)bh * 65536;

    auto stageQ = [&](int c, int buf) {
        uint32_t qb = sb + FS_Q + buf * 2 * FS_QSTG;
#pragma unroll
        for (int i = 0; i < 2; i++) {
            int idx = tid + i * 512;
            int row = idx >> 3, cc = idx & 7;
            size_t go = hbase + (size_t)(c * 128 + row) * 64 + cc * 8;
            uint32_t so = (uint32_t)row * 144 + cc * 16;
            cp16(qb + so, g_qh + go);
            cp16(qb + FS_QSTG + so, g_ql + go);
        }
    };

    // Stage K tile [32 x 64] hi+lo (plain stores)
    {
        int half = tid >> 8, idx = tid & 255;
        int row = idx >> 3, c = idx & 7;
        const __nv_bfloat16* src = (half ? g_kl : g_kh) + hbase + (size_t)(m0 + row) * 64 + c * 8;
        *(uint4*)(smf + (half ? FS_K_LO : FS_K_HI) + row * 144 + c * 16) = *(const uint4*)src;
    }
    stageQ(0, 0);
    CP_COMMIT();
    __syncthreads();

    // Preload A fragments (K tile): warp's rows = wm*16 .. +15
    const int l07 = lane & 7;
    const int b3 = (lane >> 3) & 1;
    const int b4 = lane >> 4;
    const uint32_t aOff = (uint32_t)(wm * 16 + b3 * 8 + l07) * 144 + b4 * 16;
    uint32_t ah[4][4], al[4][4];
#pragma unroll
    for (int ks = 0; ks < 4; ks++) {
        ldsm_x4(ah[ks], sb + FS_K_HI + aOff + ks * 32);
        ldsm_x4(al[ks], sb + FS_K_LO + aOff + ks * 32);
    }

    const uint32_t bOff = (uint32_t)(wn * 16 + b4 * 8 + l07) * 144 + b3 * 16;
    float acc[8][2][4];
#pragma unroll
    for (int c = 0; c < 8; c++)
#pragma unroll
        for (int nf = 0; nf < 2; nf++)
#pragma unroll
            for (int j = 0; j < 4; j++) acc[c][nf][j] = 0.f;

#pragma unroll 1
    for (int c = 0; c < 8; c++) {
        if (c < 7) { stageQ(c + 1, (c + 1) & 1); CP_COMMIT(); CP_WAIT1(); }
        else CP_WAIT0();
        __syncthreads();
        uint32_t qb = sb + FS_Q + (c & 1) * 2 * FS_QSTG;
#pragma unroll
        for (int ks = 0; ks < 4; ks++) {
            uint32_t bhf[4], blf[4];
            ldsm_x4(bhf, qb + bOff + ks * 32);
            ldsm_x4(blf, qb + FS_QSTG + bOff + ks * 32);
#pragma unroll
            for (int nf = 0; nf < 2; nf++) {
                mma_bf16(acc[c][nf], ah[ks], bhf[2 * nf], bhf[2 * nf + 1]);
                mma_bf16(acc[c][nf], al[ks], bhf[2 * nf], bhf[2 * nf + 1]);
                mma_bf16(acc[c][nf], ah[ks], blf[2 * nf], blf[2 * nf + 1]);
            }
        }
        __syncthreads();   // readers done before next stageQ overwrites
    }

    // Scale in place
#pragma unroll
    for (int c = 0; c < 8; c++)
#pragma unroll
        for (int nf = 0; nf < 2; nf++)
#pragma unroll
            for (int j = 0; j < 4; j++) acc[c][nf][j] *= SCALE_;

    const int lq = lane & 3;
    const int r0 = wm * 16 + (lane >> 2);
    const int r1 = r0 + 8;

    // Scatter scaled acc to slab (Q buffers dead; region reused)
#pragma unroll
    for (int c = 0; c < 8; c++)
#pragma unroll
        for (int nf = 0; nf < 2; nf++) {
            int col = c * 128 + wn * 16 + nf * 8 + lq * 2;
            S_s[r0 * SROW + col]     = acc[c][nf][0];
            S_s[r0 * SROW + col + 1] = acc[c][nf][1];
            S_s[r1 * SROW + col]     = acc[c][nf][2];
            S_s[r1 * SROW + col + 1] = acc[c][nf][3];
        }
    __syncthreads();

    // Warp-private Michelot sparsemax: warp w handles rows w and w+16.
    // No block barriers inside the loop.
#pragma unroll 1
    for (int rr = w; rr < 32; rr += 16) {
        const float* row = S_s + rr * SROW;
        float z[32];
#pragma unroll
        for (int j = 0; j < 32; j++) z[j] = row[j * 32 + lane];

        float s = 0.f;
#pragma unroll
        for (int j = 0; j < 32; j++) s += z[j];
#pragma unroll
        for (int o = 16; o; o >>= 1) s += __shfl_xor_sync(0xffffffffu, s, o);

        float tau = (s - 1.f) * (1.f / 1024.f);
        int cprev = 1024;
        for (int it = 0; it < 64; it++) {
            float ls = 0.f;
            int lc = 0;
#pragma unroll
            for (int j = 0; j < 32; j++)
                if (z[j] > tau) { ls += z[j]; lc++; }
#pragma unroll
            for (int o = 16; o; o >>= 1) {
                ls += __shfl_xor_sync(0xffffffffu, ls, o);
                lc += __shfl_xor_sync(0xffffffffu, lc, o);
            }
            tau = (ls - 1.f) / (float)lc;
            if (lc == cprev) break;
            cprev = lc;
        }
        if (lane == 0) tauS[rr] = tau;
    }
    __syncthreads();

    // Direct transposed output from registers (sector-coalesced: 8 lanes
    // share a column n, consecutive m): out[b, n, h*1024 + m0 + r]
    const int b = bh >> 3, h = bh & 7;
    const float t0 = tauS[r0], t1 = tauS[r1];
    const size_t ob = (size_t)b * 8388608 + (size_t)h * 1024 + m0;
#pragma unroll
    for (int c = 0; c < 8; c++)
#pragma unroll
        for (int nf = 0; nf < 2; nf++) {
            int n = c * 128 + wn * 16 + nf * 8 + lq * 2;
            out[ob + (size_t)n * 8192 + r0]       = fmaxf(acc[c][nf][0] - t0, 0.f);
            out[ob + (size_t)(n + 1) * 8192 + r0] = fmaxf(acc[c][nf][1] - t0, 0.f);
            out[ob + (size_t)n * 8192 + r1]       = fmaxf(acc[c][nf][2] - t1, 0.f);
            out[ob + (size_t)(n + 1) * 8192 + r1] = fmaxf(acc[c][nf][3] - t1, 0.f);
        }
}

// ---------------------------------------------------------------------------
extern "C" void kernel_launch(void* const* d_in, const int* in_sizes, int n_in,
                              void* d_out, int out_size) {
    (void)in_sizes; (void)n_in; (void)out_size;
    const float* x   = (const float*)d_in[0];
    const float* qw  = (const float*)d_in[1];
    const float* kw  = (const float*)d_in[2];
    const float* bnw = (const float*)d_in[3];
    const float* bnb = (const float*)d_in[4];
    float* out = (float*)d_out;

    cudaFuncSetAttribute(gemm_qk_mma,
                         cudaFuncAttributeMaxDynamicSharedMemorySize, QK_SMEM);
    cudaFuncSetAttribute(fused_scores_sparsemax,
                         cudaFuncAttributeMaxDynamicSharedMemorySize, FS_SMEM);

    split_inputs_kernel<<<2304, 256>>>(x, qw, kw);
    dim3 g1(4, 64, 2);
    gemm_qk_mma<<<g1, 256, QK_SMEM>>>();
    normalize_kernel<<<16384, 256>>>(bnw, bnb);
    dim3 g2(32, 64);
    fused_scores_sparsemax<<<g2, 512, FS_SMEM>>>(out);
}

// round 15
// speedup vs baseline: 1.4274x; 1.4274x over previous
#include <cuda_runtime.h>
#include <cuda_bf16.h>
#include <cstdint>

// Problem constants
#define B_  8
#define N_  1024
#define C_  256
#define H_  8
#define BH_ (B_ * H_)
#define HEAD_ELEMS_ 524288
#define SCALE_ 0.0625f

// Scratch (device globals)
__device__ float g_q[BH_ * N_ * 64];
__device__ float g_k[BH_ * N_ * 64];
__device__ float g_part[2048];
__device__ float g_stats[16 * 2];
__device__ int   g_ticket;
__device__ __nv_bfloat16 g_qh[BH_ * N_ * 64];
__device__ __nv_bfloat16 g_ql[BH_ * N_ * 64];
__device__ __nv_bfloat16 g_kh[BH_ * N_ * 64];
__device__ __nv_bfloat16 g_kl[BH_ * N_ * 64];
__device__ __nv_bfloat16 g_xh[8192 * 256];
__device__ __nv_bfloat16 g_xl[8192 * 256];
__device__ __nv_bfloat16 g_wh[1024 * 256];
__device__ __nv_bfloat16 g_wl[1024 * 256];
__device__ float g_scores[(size_t)8 * N_ * N_];   // rotating 32MB batch buffer

// ---------------------------------------------------------------------------
// helpers
// ---------------------------------------------------------------------------
__device__ __forceinline__ uint32_t smem_u32(const void* p) {
    uint32_t a;
    asm("{ .reg .u64 t; cvta.to.shared.u64 t, %1; cvt.u32.u64 %0, t; }" : "=r"(a) : "l"(p));
    return a;
}
__device__ __forceinline__ void ldsm_x4(uint32_t* r, uint32_t addr) {
    asm volatile("ldmatrix.sync.aligned.m8n8.x4.shared.b16 {%0,%1,%2,%3}, [%4];"
                 : "=r"(r[0]), "=r"(r[1]), "=r"(r[2]), "=r"(r[3]) : "r"(addr));
}
__device__ __forceinline__ void mma_bf16(float* c, const uint32_t* a, uint32_t b0, uint32_t b1) {
    asm volatile("mma.sync.aligned.m16n8k16.row.col.f32.bf16.bf16.f32 "
                 "{%0,%1,%2,%3},{%4,%5,%6,%7},{%8,%9},{%0,%1,%2,%3};"
                 : "+f"(c[0]), "+f"(c[1]), "+f"(c[2]), "+f"(c[3])
                 : "r"(a[0]), "r"(a[1]), "r"(a[2]), "r"(a[3]), "r"(b0), "r"(b1));
}
__device__ __forceinline__ void cp16(uint32_t d, const void* s) {
    asm volatile("cp.async.cg.shared.global [%0], [%1], 16;" :: "r"(d), "l"(s));
}
#define CP_COMMIT() asm volatile("cp.async.commit_group;" ::: "memory")
#define CP_WAIT1()  asm volatile("cp.async.wait_group 1;" ::: "memory")
#define CP_WAIT0()  asm volatile("cp.async.wait_group 0;" ::: "memory")

// ---------------------------------------------------------------------------
// Kernel 0: bf16 hi/lo split of x and [qw;kw]
// ---------------------------------------------------------------------------
__global__ void __launch_bounds__(256) split_inputs_kernel(const float* __restrict__ x,
                                                           const float* __restrict__ qw,
                                                           const float* __restrict__ kw) {
    int idx = (blockIdx.x * 256 + threadIdx.x) * 4;
    const float* src;
    __nv_bfloat16 *dh, *dl;
    int off;
    if (idx < 2097152) {
        src = x; off = idx; dh = g_xh; dl = g_xl;
    } else if (idx < 2097152 + 131072) {
        src = qw; off = idx - 2097152; dh = g_wh; dl = g_wl;
    } else {
        src = kw; off = idx - 2097152 - 131072; dh = g_wh + 131072; dl = g_wl + 131072;
    }
    float4 v = *(const float4*)(src + off);
    __nv_bfloat16 h0 = __float2bfloat16(v.x), h1 = __float2bfloat16(v.y);
    __nv_bfloat16 h2 = __float2bfloat16(v.z), h3 = __float2bfloat16(v.w);
    __nv_bfloat162 hv0, hv1, lv0, lv1;
    hv0.x = h0; hv0.y = h1; hv1.x = h2; hv1.y = h3;
    lv0.x = __float2bfloat16(v.x - __bfloat162float(h0));
    lv0.y = __float2bfloat16(v.y - __bfloat162float(h1));
    lv1.x = __float2bfloat16(v.z - __bfloat162float(h2));
    lv1.y = __float2bfloat16(v.w - __bfloat162float(h3));
    *(__nv_bfloat162*)(dh + off)     = hv0;
    *(__nv_bfloat162*)(dh + off + 2) = hv1;
    *(__nv_bfloat162*)(dl + off)     = lv0;
    *(__nv_bfloat162*)(dl + off + 2) = lv1;
}

// ---------------------------------------------------------------------------
// Kernel 1: q/k = x @ w^T, cp.async 2-stage pipeline (R10-proven).
// Epilogue folds BN partial stats; last CTA (ticket) finalizes g_stats.
// ---------------------------------------------------------------------------
#define QK_STAGE 40960
#define QK_AHI 0
#define QK_ALO 10240
#define QK_BHI 20480
#define QK_BLO 30720
#define QK_SMEM (2 * QK_STAGE)   // 81920

__global__ void __launch_bounds__(256, 2) gemm_qk_mma() {
    extern __shared__ char smq[];
    const uint32_t sb = smem_u32(smq);
    const int tid = threadIdx.x;
    const int wid = tid >> 5, lane = tid & 31;
    const int bx = blockIdx.x, by = blockIdx.y, bz = blockIdx.z;
    const int m0 = by * 128, n0 = bx * 128;
    const __nv_bfloat16* Bh = g_wh + (size_t)(bz * 512) * 256;
    const __nv_bfloat16* Bl = g_wl + (size_t)(bz * 512) * 256;

    auto stage = [&](int kc, int buf) {
        uint32_t base = sb + buf * QK_STAGE;
#pragma unroll
        for (int i = 0; i < 2; i++) {
            int idx = tid + i * 256;
            int row = idx >> 2, c = idx & 3;
            uint32_t so = (uint32_t)row * 80 + c * 16;
            size_t goA = (size_t)(m0 + row) * 256 + kc * 32 + c * 8;
            size_t goB = (size_t)(n0 + row) * 256 + kc * 32 + c * 8;
            cp16(base + QK_AHI + so, g_xh + goA);
            cp16(base + QK_ALO + so, g_xl + goA);
            cp16(base + QK_BHI + so, Bh + goB);
            cp16(base + QK_BLO + so, Bl + goB);
        }
    };

    const int wm = (wid & 3) * 32;
    const int wn = (wid >> 2) * 64;
    const int l07 = lane & 7;
    const int b3 = (lane >> 3) & 1;
    const int b4 = lane >> 4;
    const uint32_t aOff = (uint32_t)(wm + b3 * 8 + l07) * 80 + b4 * 16;
    const uint32_t bOff = (uint32_t)(wn + b4 * 8 + l07) * 80 + b3 * 16;

    float acc[2][8][4];
#pragma unroll
    for (int f = 0; f < 2; f++)
#pragma unroll
        for (int g = 0; g < 8; g++)
#pragma unroll
            for (int j = 0; j < 4; j++) acc[f][g][j] = 0.f;

    stage(0, 0);
    CP_COMMIT();

#pragma unroll 1
    for (int kc = 0; kc < 8; kc++) {
        if (kc < 7) { stage(kc + 1, (kc + 1) & 1); CP_COMMIT(); CP_WAIT1(); }
        else CP_WAIT0();
        __syncthreads();
        uint32_t base = sb + (kc & 1) * QK_STAGE;
#pragma unroll
        for (int ks = 0; ks < 2; ks++) {
            uint32_t ah[2][4], al[2][4];
#pragma unroll
            for (int f = 0; f < 2; f++) {
                ldsm_x4(ah[f], base + QK_AHI + aOff + f * 1280 + ks * 32);
                ldsm_x4(al[f], base + QK_ALO + aOff + f * 1280 + ks * 32);
            }
            uint32_t bhf[4][4], blf[4][4];
#pragma unroll
            for (int p = 0; p < 4; p++) {
                ldsm_x4(bhf[p], base + QK_BHI + bOff + p * 1280 + ks * 32);
                ldsm_x4(blf[p], base + QK_BLO + bOff + p * 1280 + ks * 32);
            }
#pragma unroll
            for (int f = 0; f < 2; f++)
#pragma unroll
                for (int p = 0; p < 4; p++) {
                    mma_bf16(acc[f][2 * p],     ah[f], bhf[p][0], bhf[p][1]);
                    mma_bf16(acc[f][2 * p],     al[f], bhf[p][0], bhf[p][1]);
                    mma_bf16(acc[f][2 * p],     ah[f], blf[p][0], blf[p][1]);
                    mma_bf16(acc[f][2 * p + 1], ah[f], bhf[p][2], bhf[p][3]);
                    mma_bf16(acc[f][2 * p + 1], al[f], bhf[p][2], bhf[p][3]);
                    mma_bf16(acc[f][2 * p + 1], ah[f], blf[p][2], blf[p][3]);
                }
        }
        __syncthreads();
    }

    float* outp = bz ? g_k : g_q;
    const int r0 = m0 + wm + (lane >> 2);
    const int c0 = n0 + wn + (lane & 3) * 2;
    float s1 = 0.f, s2 = 0.f;
#pragma unroll
    for (int f = 0; f < 2; f++)
#pragma unroll
        for (int g = 0; g < 8; g++) {
            int col = c0 + g * 8;
            int h = col >> 6, d = col & 63;
#pragma unroll
            for (int u = 0; u < 2; u++) {
                float v0 = acc[f][g][u * 2], v1 = acc[f][g][u * 2 + 1];
                s1 += v0 + v1;
                s2 += v0 * v0 + v1 * v1;
                int row = r0 + f * 16 + u * 8;
                int bb = row >> 10, nn = row & 1023;
                float* dst = outp + ((size_t)(bb * H_ + h) << 16) + nn * 64 + d;
                *(float2*)dst = make_float2(v0, v1);
            }
        }
#pragma unroll
    for (int o = 16; o; o >>= 1) {
        s1 += __shfl_xor_sync(0xffffffffu, s1, o);
        s2 += __shfl_xor_sync(0xffffffffu, s2, o);
    }
    __shared__ float wsum[8], wsq[8];
    __shared__ int islast;
    if (lane == 0) { wsum[wid] = s1; wsq[wid] = s2; }
    __syncthreads();
    if (tid == 0) {
        int slot = ((bz * 4 + bx) * 64 + by) * 4;
        g_part[slot + 0] = wsum[0] + wsum[1] + wsum[2] + wsum[3];
        g_part[slot + 1] = wsq[0] + wsq[1] + wsq[2] + wsq[3];
        g_part[slot + 2] = wsum[4] + wsum[5] + wsum[6] + wsum[7];
        g_part[slot + 3] = wsq[4] + wsq[5] + wsq[6] + wsq[7];
        __threadfence();
        islast = (atomicAdd(&g_ticket, 1) == 511);
    }
    __syncthreads();
    if (islast) {
        __threadfence();
        if (tid < 16) {
            int t = tid >> 3, h = tid & 7;
            int bx2 = h >> 1, sel = h & 1;
            float a = 0.f, c2 = 0.f;
            for (int by2 = 0; by2 < 64; by2++) {
                int slot = ((t * 4 + bx2) * 64 + by2) * 4 + sel * 2;
                a += g_part[slot];
                c2 += g_part[slot + 1];
            }
            float mean = a * (1.f / (float)HEAD_ELEMS_);
            float var = c2 * (1.f / (float)HEAD_ELEMS_) - mean * mean;
            g_stats[tid * 2] = mean;
            g_stats[tid * 2 + 1] = rsqrtf(var + 1e-5f);
        }
        if (tid == 0) g_ticket = 0;
    }
}

// ---------------------------------------------------------------------------
// Kernel 2: BN + L2 normalize; emit bf16 hi/lo split.
// ---------------------------------------------------------------------------
__global__ void __launch_bounds__(256) normalize_kernel(const float* __restrict__ bnw,
                                                        const float* __restrict__ bnb) {
    int gw = (blockIdx.x * blockDim.x + threadIdx.x) >> 5;
    int lane = threadIdx.x & 31;
    int t = gw >> 16;
    int rem = gw & 65535;
    int h = (rem >> 10) & 7;
    const float* p = (t ? g_k : g_q) + (size_t)rem * 64;
    float mean = g_stats[(t * 8 + h) * 2];
    float rstd = g_stats[(t * 8 + h) * 2 + 1];
    float w = bnw[h], bia = bnb[h];
    float2 v = *(const float2*)(p + lane * 2);
    float x0 = (v.x - mean) * rstd * w + bia;
    float x1 = (v.y - mean) * rstd * w + bia;
    float ss = x0 * x0 + x1 * x1;
#pragma unroll
    for (int o = 16; o; o >>= 1) ss += __shfl_xor_sync(0xffffffffu, ss, o);
    float inv = 1.f / fmaxf(sqrtf(ss), 1e-12f);
    x0 *= inv; x1 *= inv;

    __nv_bfloat16 h0 = __float2bfloat16(x0);
    __nv_bfloat16 h1 = __float2bfloat16(x1);
    __nv_bfloat16 l0 = __float2bfloat16(x0 - __bfloat162float(h0));
    __nv_bfloat16 l1 = __float2bfloat16(x1 - __bfloat162float(h1));
    size_t off = (size_t)rem * 64 + lane * 2;
    __nv_bfloat162 hv; hv.x = h0; hv.y = h1;
    __nv_bfloat162 lv; lv.x = l0; lv.y = l1;
    if (t) {
        *(__nv_bfloat162*)(g_kh + off) = hv;
        *(__nv_bfloat162*)(g_kl + off) = lv;
    } else {
        *(__nv_bfloat162*)(g_qh + off) = hv;
        *(__nv_bfloat162*)(g_ql + off) = lv;
    }
}

// ---------------------------------------------------------------------------
// Kernel 4 (R11-proven, batched): scores GEMM into a 32MB L2-resident slice.
// bh = bh0 + blockIdx.z; slice index = blockIdx.z.
// ---------------------------------------------------------------------------
#define RS 144
#define SM_A_HI 0
#define SM_A_LO (128 * RS)
#define SM_B_HI (2 * 128 * RS)
#define SM_B_LO (3 * 128 * RS)
#define SM_TOTAL (4 * 128 * RS)  // 73728

__global__ void __launch_bounds__(256) gemm_scores_mma(int bh0) {
    extern __shared__ char sm4[];
    const int tid = threadIdx.x;
    const int wid = tid >> 5, lane = tid & 31;
    const int bhl = blockIdx.z;
    const int bh = bh0 + bhl;
    const int m0 = blockIdx.y * 128;
    const int n0 = blockIdx.x * 128;

    {
        const size_t hb = (size_t)bh * 65536;
        const uint4* sAh = (const uint4*)(g_kh + hb + (size_t)m0 * 64);
        const uint4* sAl = (const uint4*)(g_kl + hb + (size_t)m0 * 64);
        const uint4* sBh = (const uint4*)(g_qh + hb + (size_t)n0 * 64);
        const uint4* sBl = (const uint4*)(g_ql + hb + (size_t)n0 * 64);
#pragma unroll
        for (int i = 0; i < 4; i++) {
            int idx = tid + i * 256;
            int row = idx >> 3, c = idx & 7;
            uint32_t so = row * RS + c * 16;
            *(uint4*)(sm4 + SM_A_HI + so) = sAh[idx];
            *(uint4*)(sm4 + SM_A_LO + so) = sAl[idx];
            *(uint4*)(sm4 + SM_B_HI + so) = sBh[idx];
            *(uint4*)(sm4 + SM_B_LO + so) = sBl[idx];
        }
    }
    __syncthreads();

    const uint32_t sb = smem_u32(sm4);
    const int wm = (wid & 3) * 32;
    const int wn = (wid >> 2) * 64;
    const int l07 = lane & 7;
    const int b3 = (lane >> 3) & 1;
    const int b4 = lane >> 4;
    const uint32_t aOff = (uint32_t)(wm + b3 * 8 + l07) * RS + b4 * 16;
    const uint32_t bOff = (uint32_t)(wn + b4 * 8 + l07) * RS + b3 * 16;

    float acc[2][8][4];
#pragma unroll
    for (int f = 0; f < 2; f++)
#pragma unroll
        for (int g = 0; g < 8; g++)
#pragma unroll
            for (int j = 0; j < 4; j++) acc[f][g][j] = 0.f;

#pragma unroll
    for (int ks = 0; ks < 4; ks++) {
        uint32_t ah[2][4], al[2][4];
#pragma unroll
        for (int f = 0; f < 2; f++) {
            ldsm_x4(ah[f], sb + SM_A_HI + aOff + f * (16 * RS) + ks * 32);
            ldsm_x4(al[f], sb + SM_A_LO + aOff + f * (16 * RS) + ks * 32);
        }
        uint32_t bhf[4][4], blf[4][4];
#pragma unroll
        for (int p = 0; p < 4; p++) {
            ldsm_x4(bhf[p], sb + SM_B_HI + bOff + p * (16 * RS) + ks * 32);
            ldsm_x4(blf[p], sb + SM_B_LO + bOff + p * (16 * RS) + ks * 32);
        }
#pragma unroll
        for (int f = 0; f < 2; f++)
#pragma unroll
            for (int p = 0; p < 4; p++) {
                mma_bf16(acc[f][2 * p],     ah[f], bhf[p][0], bhf[p][1]);
                mma_bf16(acc[f][2 * p],     al[f], bhf[p][0], bhf[p][1]);
                mma_bf16(acc[f][2 * p],     ah[f], blf[p][0], blf[p][1]);
                mma_bf16(acc[f][2 * p + 1], ah[f], bhf[p][2], bhf[p][3]);
                mma_bf16(acc[f][2 * p + 1], al[f], bhf[p][2], bhf[p][3]);
                mma_bf16(acc[f][2 * p + 1], ah[f], blf[p][2], blf[p][3]);
            }
    }

    float* Cp = g_scores + (size_t)bhl * 1048576;
    const int r0 = m0 + wm + (lane >> 2);
    const int c0 = n0 + wn + (lane & 3) * 2;
#pragma unroll
    for (int f = 0; f < 2; f++)
#pragma unroll
        for (int g = 0; g < 8; g++) {
            float* d0 = Cp + (size_t)(r0 + f * 16) * 1024 + c0 + g * 8;
            *(float2*)d0 = make_float2(acc[f][g][0] * SCALE_, acc[f][g][1] * SCALE_);
            *(float2*)(d0 + 8 * 1024) = make_float2(acc[f][g][2] * SCALE_, acc[f][g][3] * SCALE_);
        }
}

// ---------------------------------------------------------------------------
// Kernel 5 (R11-proven, batched): sparsemax reading the L2-resident slice.
// ---------------------------------------------------------------------------
__global__ void __launch_bounds__(1024) sparsemax_kernel(float* __restrict__ out, int bh0) {
    __shared__ float tile[128][33];
    const int bid = blockIdx.x;            // 256 = 8 bh-local * 32 mblocks
    const int bhl = bid >> 5;
    const int bh = bh0 + bhl;
    const int mblk = bid & 31;
    const int b = bh >> 3, h = bh & 7;
    const int w = threadIdx.x >> 5, lane = threadIdx.x & 31;
    const int m = mblk * 32 + w;
    const float* row = g_scores + (size_t)bhl * 1048576 + (size_t)m * 1024;

    float z[32];
#pragma unroll
    for (int j = 0; j < 32; j++) z[j] = row[j * 32 + lane];

    float mx = z[0];
#pragma unroll
    for (int j = 1; j < 32; j++) mx = fmaxf(mx, z[j]);
#pragma unroll
    for (int o = 16; o; o >>= 1) mx = fmaxf(mx, __shfl_xor_sync(0xffffffffu, mx, o));
#pragma unroll
    for (int j = 0; j < 32; j++) z[j] -= mx;

    float s = 0.f;
#pragma unroll
    for (int j = 0; j < 32; j++) s += z[j];
#pragma unroll
    for (int o = 16; o; o >>= 1) s += __shfl_xor_sync(0xffffffffu, s, o);

    float tau = (s - 1.f) * (1.f / 1024.f);
    int cprev = 1024;
    for (int it = 0; it < 64; it++) {
        float ls = 0.f;
        int lc = 0;
#pragma unroll
        for (int j = 0; j < 32; j++)
            if (z[j] > tau) { ls += z[j]; lc++; }
#pragma unroll
        for (int o = 16; o; o >>= 1) {
            ls += __shfl_xor_sync(0xffffffffu, ls, o);
            lc += __shfl_xor_sync(0xffffffffu, lc, o);
        }
        tau = (ls - 1.f) / (float)lc;
        if (lc == cprev) break;
        cprev = lc;
    }

#pragma unroll
    for (int j = 0; j < 32; j++) z[j] = fmaxf(z[j] - tau, 0.f);

    const size_t outbase = (size_t)b * ((size_t)N_ * 8192) + (size_t)h * 1024 + mblk * 32;
#pragma unroll 1
    for (int g = 0; g < 8; g++) {
#pragma unroll
        for (int q = 0; q < 4; q++) tile[q * 32 + lane][w] = z[g * 4 + q];
        __syncthreads();
#pragma unroll
        for (int k = 0; k < 4; k++) {
            int flat = threadIdx.x + k * 1024;
            int nl = flat >> 5, ml = flat & 31;
            out[outbase + (size_t)(g * 128 + nl) * 8192 + ml] = tile[nl][ml];
        }
        __syncthreads();
    }
}

// ---------------------------------------------------------------------------
extern "C" void kernel_launch(void* const* d_in, const int* in_sizes, int n_in,
                              void* d_out, int out_size) {
    (void)in_sizes; (void)n_in; (void)out_size;
    const float* x   = (const float*)d_in[0];
    const float* qw  = (const float*)d_in[1];
    const float* kw  = (const float*)d_in[2];
    const float* bnw = (const float*)d_in[3];
    const float* bnb = (const float*)d_in[4];
    float* out = (float*)d_out;

    cudaFuncSetAttribute(gemm_qk_mma,
                         cudaFuncAttributeMaxDynamicSharedMemorySize, QK_SMEM);
    cudaFuncSetAttribute(gemm_scores_mma,
                         cudaFuncAttributeMaxDynamicSharedMemorySize, SM_TOTAL);

    split_inputs_kernel<<<2304, 256>>>(x, qw, kw);
    dim3 g1(4, 64, 2);
    gemm_qk_mma<<<g1, 256, QK_SMEM>>>();
    normalize_kernel<<<16384, 256>>>(bnw, bnb);

    dim3 gsc(8, 8, 8);                     // n-tiles, m-tiles, 8 bh per batch
    for (int bt = 0; bt < 8; bt++) {
        gemm_scores_mma<<<gsc, 256, SM_TOTAL>>>(bt * 8);
        sparsemax_kernel<<<256, 1024>>>(out, bt * 8);
    }
}

// round 16
// speedup vs baseline: 1.5346x; 1.0751x over previous
#include <cuda_runtime.h>
#include <cuda_bf16.h>
#include <cstdint>

// Problem constants
#define B_  8
#define N_  1024
#define C_  256
#define H_  8
#define BH_ (B_ * H_)
#define HEAD_ELEMS_ 524288
#define SCALE_ 0.0625f

// Scratch (device globals)
__device__ float g_q[BH_ * N_ * 64];
__device__ float g_k[BH_ * N_ * 64];
__device__ float g_part[2048];
__device__ float g_stats[16 * 2];
__device__ int   g_ticket;
__device__ __nv_bfloat16 g_qh[BH_ * N_ * 64];
__device__ __nv_bfloat16 g_ql[BH_ * N_ * 64];
__device__ __nv_bfloat16 g_kh[BH_ * N_ * 64];
__device__ __nv_bfloat16 g_kl[BH_ * N_ * 64];
__device__ __nv_bfloat16 g_xh[8192 * 256];
__device__ __nv_bfloat16 g_xl[8192 * 256];
__device__ __nv_bfloat16 g_wh[1024 * 256];
__device__ __nv_bfloat16 g_wl[1024 * 256];

// ---------------------------------------------------------------------------
// helpers
// ---------------------------------------------------------------------------
__device__ __forceinline__ uint32_t smem_u32(const void* p) {
    uint32_t a;
    asm("{ .reg .u64 t; cvta.to.shared.u64 t, %1; cvt.u32.u64 %0, t; }" : "=r"(a) : "l"(p));
    return a;
}
__device__ __forceinline__ void ldsm_x4(uint32_t* r, uint32_t addr) {
    asm volatile("ldmatrix.sync.aligned.m8n8.x4.shared.b16 {%0,%1,%2,%3}, [%4];"
                 : "=r"(r[0]), "=r"(r[1]), "=r"(r[2]), "=r"(r[3]) : "r"(addr));
}
__device__ __forceinline__ void mma_bf16(float* c, const uint32_t* a, uint32_t b0, uint32_t b1) {
    asm volatile("mma.sync.aligned.m16n8k16.row.col.f32.bf16.bf16.f32 "
                 "{%0,%1,%2,%3},{%4,%5,%6,%7},{%8,%9},{%0,%1,%2,%3};"
                 : "+f"(c[0]), "+f"(c[1]), "+f"(c[2]), "+f"(c[3])
                 : "r"(a[0]), "r"(a[1]), "r"(a[2]), "r"(a[3]), "r"(b0), "r"(b1));
}
__device__ __forceinline__ void cp16(uint32_t d, const void* s) {
    asm volatile("cp.async.cg.shared.global [%0], [%1], 16;" :: "r"(d), "l"(s));
}
#define CP_COMMIT() asm volatile("cp.async.commit_group;" ::: "memory")
#define CP_WAIT1()  asm volatile("cp.async.wait_group 1;" ::: "memory")
#define CP_WAIT0()  asm volatile("cp.async.wait_group 0;" ::: "memory")

// ---------------------------------------------------------------------------
// Kernel 0: bf16 hi/lo split of x and [qw;kw]
// ---------------------------------------------------------------------------
__global__ void __launch_bounds__(256) split_inputs_kernel(const float* __restrict__ x,
                                                           const float* __restrict__ qw,
                                                           const float* __restrict__ kw) {
    int idx = (blockIdx.x * 256 + threadIdx.x) * 4;
    const float* src;
    __nv_bfloat16 *dh, *dl;
    int off;
    if (idx < 2097152) {
        src = x; off = idx; dh = g_xh; dl = g_xl;
    } else if (idx < 2097152 + 131072) {
        src = qw; off = idx - 2097152; dh = g_wh; dl = g_wl;
    } else {
        src = kw; off = idx - 2097152 - 131072; dh = g_wh + 131072; dl = g_wl + 131072;
    }
    float4 v = *(const float4*)(src + off);
    __nv_bfloat16 h0 = __float2bfloat16(v.x), h1 = __float2bfloat16(v.y);
    __nv_bfloat16 h2 = __float2bfloat16(v.z), h3 = __float2bfloat16(v.w);
    __nv_bfloat162 hv0, hv1, lv0, lv1;
    hv0.x = h0; hv0.y = h1; hv1.x = h2; hv1.y = h3;
    lv0.x = __float2bfloat16(v.x - __bfloat162float(h0));
    lv0.y = __float2bfloat16(v.y - __bfloat162float(h1));
    lv1.x = __float2bfloat16(v.z - __bfloat162float(h2));
    lv1.y = __float2bfloat16(v.w - __bfloat162float(h3));
    *(__nv_bfloat162*)(dh + off)     = hv0;
    *(__nv_bfloat162*)(dh + off + 2) = hv1;
    *(__nv_bfloat162*)(dl + off)     = lv0;
    *(__nv_bfloat162*)(dl + off + 2) = lv1;
}

// ---------------------------------------------------------------------------
// Kernel 1: q/k = x @ w^T, cp.async 2-stage pipeline (R10-proven).
// Epilogue folds BN partial stats; last CTA (ticket) finalizes g_stats.
// ---------------------------------------------------------------------------
#define QK_STAGE 40960
#define QK_AHI 0
#define QK_ALO 10240
#define QK_BHI 20480
#define QK_BLO 30720
#define QK_SMEM (2 * QK_STAGE)   // 81920

__global__ void __launch_bounds__(256, 2) gemm_qk_mma() {
    extern __shared__ char smq[];
    const uint32_t sb = smem_u32(smq);
    const int tid = threadIdx.x;
    const int wid = tid >> 5, lane = tid & 31;
    const int bx = blockIdx.x, by = blockIdx.y, bz = blockIdx.z;
    const int m0 = by * 128, n0 = bx * 128;
    const __nv_bfloat16* Bh = g_wh + (size_t)(bz * 512) * 256;
    const __nv_bfloat16* Bl = g_wl + (size_t)(bz * 512) * 256;

    auto stage = [&](int kc, int buf) {
        uint32_t base = sb + buf * QK_STAGE;
#pragma unroll
        for (int i = 0; i < 2; i++) {
            int idx = tid + i * 256;
            int row = idx >> 2, c = idx & 3;
            uint32_t so = (uint32_t)row * 80 + c * 16;
            size_t goA = (size_t)(m0 + row) * 256 + kc * 32 + c * 8;
            size_t goB = (size_t)(n0 + row) * 256 + kc * 32 + c * 8;
            cp16(base + QK_AHI + so, g_xh + goA);
            cp16(base + QK_ALO + so, g_xl + goA);
            cp16(base + QK_BHI + so, Bh + goB);
            cp16(base + QK_BLO + so, Bl + goB);
        }
    };

    const int wm = (wid & 3) * 32;
    const int wn = (wid >> 2) * 64;
    const int l07 = lane & 7;
    const int b3 = (lane >> 3) & 1;
    const int b4 = lane >> 4;
    const uint32_t aOff = (uint32_t)(wm + b3 * 8 + l07) * 80 + b4 * 16;
    const uint32_t bOff = (uint32_t)(wn + b4 * 8 + l07) * 80 + b3 * 16;

    float acc[2][8][4];
#pragma unroll
    for (int f = 0; f < 2; f++)
#pragma unroll
        for (int g = 0; g < 8; g++)
#pragma unroll
            for (int j = 0; j < 4; j++) acc[f][g][j] = 0.f;

    stage(0, 0);
    CP_COMMIT();

#pragma unroll 1
    for (int kc = 0; kc < 8; kc++) {
        if (kc < 7) { stage(kc + 1, (kc + 1) & 1); CP_COMMIT(); CP_WAIT1(); }
        else CP_WAIT0();
        __syncthreads();
        uint32_t base = sb + (kc & 1) * QK_STAGE;
#pragma unroll
        for (int ks = 0; ks < 2; ks++) {
            uint32_t ah[2][4], al[2][4];
#pragma unroll
            for (int f = 0; f < 2; f++) {
                ldsm_x4(ah[f], base + QK_AHI + aOff + f * 1280 + ks * 32);
                ldsm_x4(al[f], base + QK_ALO + aOff + f * 1280 + ks * 32);
            }
            uint32_t bhf[4][4], blf[4][4];
#pragma unroll
            for (int p = 0; p < 4; p++) {
                ldsm_x4(bhf[p], base + QK_BHI + bOff + p * 1280 + ks * 32);
                ldsm_x4(blf[p], base + QK_BLO + bOff + p * 1280 + ks * 32);
            }
#pragma unroll
            for (int f = 0; f < 2; f++)
#pragma unroll
                for (int p = 0; p < 4; p++) {
                    mma_bf16(acc[f][2 * p],     ah[f], bhf[p][0], bhf[p][1]);
                    mma_bf16(acc[f][2 * p],     al[f], bhf[p][0], bhf[p][1]);
                    mma_bf16(acc[f][2 * p],     ah[f], blf[p][0], blf[p][1]);
                    mma_bf16(acc[f][2 * p + 1], ah[f], bhf[p][2], bhf[p][3]);
                    mma_bf16(acc[f][2 * p + 1], al[f], bhf[p][2], bhf[p][3]);
                    mma_bf16(acc[f][2 * p + 1], ah[f], blf[p][2], blf[p][3]);
                }
        }
        __syncthreads();
    }

    float* outp = bz ? g_k : g_q;
    const int r0 = m0 + wm + (lane >> 2);
    const int c0 = n0 + wn + (lane & 3) * 2;
    float s1 = 0.f, s2 = 0.f;
#pragma unroll
    for (int f = 0; f < 2; f++)
#pragma unroll
        for (int g = 0; g < 8; g++) {
            int col = c0 + g * 8;
            int h = col >> 6, d = col & 63;
#pragma unroll
            for (int u = 0; u < 2; u++) {
                float v0 = acc[f][g][u * 2], v1 = acc[f][g][u * 2 + 1];
                s1 += v0 + v1;
                s2 += v0 * v0 + v1 * v1;
                int row = r0 + f * 16 + u * 8;
                int bb = row >> 10, nn = row & 1023;
                float* dst = outp + ((size_t)(bb * H_ + h) << 16) + nn * 64 + d;
                *(float2*)dst = make_float2(v0, v1);
            }
        }
#pragma unroll
    for (int o = 16; o; o >>= 1) {
        s1 += __shfl_xor_sync(0xffffffffu, s1, o);
        s2 += __shfl_xor_sync(0xffffffffu, s2, o);
    }
    __shared__ float wsum[8], wsq[8];
    __shared__ int islast;
    if (lane == 0) { wsum[wid] = s1; wsq[wid] = s2; }
    __syncthreads();
    if (tid == 0) {
        int slot = ((bz * 4 + bx) * 64 + by) * 4;
        g_part[slot + 0] = wsum[0] + wsum[1] + wsum[2] + wsum[3];
        g_part[slot + 1] = wsq[0] + wsq[1] + wsq[2] + wsq[3];
        g_part[slot + 2] = wsum[4] + wsum[5] + wsum[6] + wsum[7];
        g_part[slot + 3] = wsq[4] + wsq[5] + wsq[6] + wsq[7];
        __threadfence();
        islast = (atomicAdd(&g_ticket, 1) == 511);
    }
    __syncthreads();
    if (islast) {
        __threadfence();
        if (tid < 16) {
            int t = tid >> 3, h = tid & 7;
            int bx2 = h >> 1, sel = h & 1;
            float a = 0.f, c2 = 0.f;
            for (int by2 = 0; by2 < 64; by2++) {
                int slot = ((t * 4 + bx2) * 64 + by2) * 4 + sel * 2;
                a += g_part[slot];
                c2 += g_part[slot + 1];
            }
            float mean = a * (1.f / (float)HEAD_ELEMS_);
            float var = c2 * (1.f / (float)HEAD_ELEMS_) - mean * mean;
            g_stats[tid * 2] = mean;
            g_stats[tid * 2 + 1] = rsqrtf(var + 1e-5f);
        }
        if (tid == 0) g_ticket = 0;
    }
}

// ---------------------------------------------------------------------------
// Kernel 2: BN + L2 normalize; emit bf16 hi/lo split.
// ---------------------------------------------------------------------------
__global__ void __launch_bounds__(256) normalize_kernel(const float* __restrict__ bnw,
                                                        const float* __restrict__ bnb) {
    int gw = (blockIdx.x * blockDim.x + threadIdx.x) >> 5;
    int lane = threadIdx.x & 31;
    int t = gw >> 16;
    int rem = gw & 65535;
    int h = (rem >> 10) & 7;
    const float* p = (t ? g_k : g_q) + (size_t)rem * 64;
    float mean = g_stats[(t * 8 + h) * 2];
    float rstd = g_stats[(t * 8 + h) * 2 + 1];
    float w = bnw[h], bia = bnb[h];
    float2 v = *(const float2*)(p + lane * 2);
    float x0 = (v.x - mean) * rstd * w + bia;
    float x1 = (v.y - mean) * rstd * w + bia;
    float ss = x0 * x0 + x1 * x1;
#pragma unroll
    for (int o = 16; o; o >>= 1) ss += __shfl_xor_sync(0xffffffffu, ss, o);
    float inv = 1.f / fmaxf(sqrtf(ss), 1e-12f);
    x0 *= inv; x1 *= inv;

    __nv_bfloat16 h0 = __float2bfloat16(x0);
    __nv_bfloat16 h1 = __float2bfloat16(x1);
    __nv_bfloat16 l0 = __float2bfloat16(x0 - __bfloat162float(h0));
    __nv_bfloat16 l1 = __float2bfloat16(x1 - __bfloat162float(h1));
    size_t off = (size_t)rem * 64 + lane * 2;
    __nv_bfloat162 hv; hv.x = h0; hv.y = h1;
    __nv_bfloat162 lv; lv.x = l0; lv.y = l1;
    if (t) {
        *(__nv_bfloat162*)(g_kh + off) = hv;
        *(__nv_bfloat162*)(g_kl + off) = lv;
    } else {
        *(__nv_bfloat162*)(g_qh + off) = hv;
        *(__nv_bfloat162*)(g_ql + off) = lv;
    }
}

// ---------------------------------------------------------------------------
// Kernel 3 (fused v5): 16-row m-tiles, 512 thr, 2 CTAs/SM (reg budget 64).
// acc = 32 regs; A frags re-loaded per ks; B frags direct from global
// (R10-proven mapping). Sparsemax: ONE row per warp. Out via slab, 64B
// coalesced stores.
// ---------------------------------------------------------------------------
#define FS_K_HI 0
#define FS_K_LO 2304
#define FS_SLAB 4608
#define SROW 1025
#define FS_TAUS (FS_SLAB + 16 * SROW * 4)   // 70208
#define FS_SMEM (FS_TAUS + 64)              // 70272 (x2 CTAs = 140544)

__global__ void __launch_bounds__(512, 2) fused_scores_sparsemax(float* __restrict__ out) {
    extern __shared__ char smf[];
    const uint32_t sb = smem_u32(smf);
    float* S_s  = (float*)(smf + FS_SLAB);
    float* tauS = (float*)(smf + FS_TAUS);

    const int tid = threadIdx.x;
    const int w = tid >> 5, lane = tid & 31;
    const int bh = blockIdx.y;
    const int m0 = blockIdx.x * 16;
    const size_t hbase = (size_t)bh * 65536;
    const __nv_bfloat16* Qh = g_qh + hbase;
    const __nv_bfloat16* Ql = g_ql + hbase;

    // Stage K tile [16 x 64] hi+lo (256 threads; 144B rows for ldmatrix)
    if (tid < 256) {
        int half = tid >> 7;               // 0: hi, 1: lo
        int idx = tid & 127;               // 16 rows x 8 chunks
        int row = idx >> 3, c = idx & 7;
        const __nv_bfloat16* src = (half ? g_kl : g_kh) + hbase + (size_t)(m0 + row) * 64 + c * 8;
        *(uint4*)(smf + (half ? FS_K_LO : FS_K_HI) + row * 144 + c * 16) = *(const uint4*)src;
    }
    __syncthreads();

    // Warp w covers cols [w*64, w*64+64). A = 16 K-rows (single m16 frag).
    const int l07 = lane & 7;
    const int b3 = (lane >> 3) & 1;
    const int b4 = lane >> 4;
    const uint32_t aOff = (uint32_t)(b3 * 8 + l07) * 144 + b4 * 16;
    const int nq = lane >> 2;              // B fragment row within 8-group
    const int kq = (lane & 3) * 2;         // B fragment k offset

    float acc[8][4];
#pragma unroll
    for (int p = 0; p < 8; p++)
#pragma unroll
        for (int j = 0; j < 4; j++) acc[p][j] = 0.f;

#pragma unroll
    for (int ks = 0; ks < 4; ks++) {
        uint32_t ah[4], al[4];
        ldsm_x4(ah, sb + FS_K_HI + aOff + ks * 32);
        ldsm_x4(al, sb + FS_K_LO + aOff + ks * 32);
#pragma unroll
        for (int p = 0; p < 8; p++) {
            size_t go = (size_t)(w * 64 + p * 8 + nq) * 64 + ks * 16 + kq;
            uint32_t bh0 = *(const uint32_t*)(Qh + go);
            uint32_t bh1 = *(const uint32_t*)(Qh + go + 8);
            uint32_t bl0 = *(const uint32_t*)(Ql + go);
            uint32_t bl1 = *(const uint32_t*)(Ql + go + 8);
            mma_bf16(acc[p], ah, bh0, bh1);
            mma_bf16(acc[p], al, bh0, bh1);
            mma_bf16(acc[p], ah, bl0, bl1);
        }
    }

    // Scale + scatter to slab
    const int r0 = lane >> 2;              // rows 0..7
    const int r1 = r0 + 8;
#pragma unroll
    for (int p = 0; p < 8; p++) {
        int col = w * 64 + p * 8 + kq;
        S_s[r0 * SROW + col]     = acc[p][0] * SCALE_;
        S_s[r0 * SROW + col + 1] = acc[p][1] * SCALE_;
        S_s[r1 * SROW + col]     = acc[p][2] * SCALE_;
        S_s[r1 * SROW + col + 1] = acc[p][3] * SCALE_;
    }
    __syncthreads();

    // Sparsemax: warp w owns row w (one row per warp, no serial loop)
    {
        const float* rowp = S_s + w * SROW;
        float z[32];
#pragma unroll
        for (int j = 0; j < 32; j++) z[j] = rowp[j * 32 + lane];

        float s = 0.f;
#pragma unroll
        for (int j = 0; j < 32; j++) s += z[j];
#pragma unroll
        for (int o = 16; o; o >>= 1) s += __shfl_xor_sync(0xffffffffu, s, o);

        float tau = (s - 1.f) * (1.f / 1024.f);
        int cprev = 1024;
        for (int it = 0; it < 64; it++) {
            float ls = 0.f;
            int lc = 0;
#pragma unroll
            for (int j = 0; j < 32; j++)
                if (z[j] > tau) { ls += z[j]; lc++; }
#pragma unroll
            for (int o = 16; o; o >>= 1) {
                ls += __shfl_xor_sync(0xffffffffu, ls, o);
                lc += __shfl_xor_sync(0xffffffffu, lc, o);
            }
            tau = (ls - 1.f) / (float)lc;
            if (lc == cprev) break;
            cprev = lc;
        }
        if (lane == 0) tauS[w] = tau;
    }
    __syncthreads();

    // Output: warp w writes cols n = w*64..w*64+63; half-warps write 2 cols
    // per step, 16 consecutive m each (64B coalesced stores).
    const int b = bh >> 3, h = bh & 7;
    const size_t ob = (size_t)b * 8388608 + (size_t)h * 1024 + m0;
    const int mo = lane & 15;
    const int nh = lane >> 4;
    const float tm = tauS[mo];
#pragma unroll 8
    for (int i = 0; i < 32; i++) {
        int n = w * 64 + 2 * i + nh;
        float v = S_s[mo * SROW + n] - tm;
        out[ob + (size_t)n * 8192 + mo] = fmaxf(v, 0.f);
    }
}

// ---------------------------------------------------------------------------
extern "C" void kernel_launch(void* const* d_in, const int* in_sizes, int n_in,
                              void* d_out, int out_size) {
    (void)in_sizes; (void)n_in; (void)out_size;
    const float* x   = (const float*)d_in[0];
    const float* qw  = (const float*)d_in[1];
    const float* kw  = (const float*)d_in[2];
    const float* bnw = (const float*)d_in[3];
    const float* bnb = (const float*)d_in[4];
    float* out = (float*)d_out;

    cudaFuncSetAttribute(gemm_qk_mma,
                         cudaFuncAttributeMaxDynamicSharedMemorySize, QK_SMEM);
    cudaFuncSetAttribute(fused_scores_sparsemax,
                         cudaFuncAttributeMaxDynamicSharedMemorySize, FS_SMEM);

    split_inputs_kernel<<<2304, 256>>>(x, qw, kw);
    dim3 g1(4, 64, 2);
    gemm_qk_mma<<<g1, 256, QK_SMEM>>>();
    normalize_kernel<<<16384, 256>>>(bnw, bnb);
    dim3 g2(64, 64);                          // 16-row m-tiles, bh
    fused_scores_sparsemax<<<g2, 512, FS_SMEM>>>(out);
}